// round 8
// baseline (speedup 1.0000x reference)
#include <cuda_runtime.h>

// Per-batch exact integer accumulators: [n] = {sum_y(=Σ R*i), sum_x(=Σ R*j), count}
// Zero at module load; the final block re-zeroes after reading, so every graph
// replay starts clean (deterministic: integer adds are order-independent).
__device__ int g_acc[64][3];
__device__ float g_ts[64][2];   // target center sums, written by block 0 each run
__device__ int g_done;          // arrival counter, reset by the final block

// ---------------------------------------------------------------------------
// Batched-load 8-row strip: load ALL 10 rows (8 compute + 2 halo) into a
// register array first (front-batched LDG.128 -> high MLP), then compute.
// Peak(i,j) <=> B[j] > max(vAC[j], vm3[j-1], vm3[j+1]).
// ---------------------------------------------------------------------------
template<int W, int R, int LANE_W>
__device__ __forceinline__ void process_strip8(
    const float* __restrict__ img,   // channel-2 base for this batch
    int n, int i_begin, int i_end, int col_base)
{
    constexpr bool HALO = (4 * LANE_W < W);   // only p1 (two 128-col strips)
    const int lane = threadIdx.x & 31;
    const int li   = lane % LANE_W;
    const unsigned shfl_mask = (LANE_W == 32) ? 0xFFFFFFFFu
                                              : (0xFFFFu << (lane & 16));
    const int col0 = col_base + 4 * li;
    const bool hl = HALO && (col_base > 0) && (li == 0);
    const bool hr = HALO && (col_base + 4 * LANE_W < W) && (li == LANE_W - 1);
    const bool m0 = (col0 == 0);          // element 0 on image edge
    const bool m3 = (col0 + 3 == W - 1);  // element 3 on image edge
    const float* p = img + col0;

    // ---- load phase: 10 rows, clamped (duplicates for short strips hit L1) ----
    float4 rv[10];
#pragma unroll
    for (int k = 0; k < 10; ++k) {
        int r = i_begin - 1 + k; if (r > i_end + 1) r = i_end + 1;
        rv[k] = __ldg((const float4*)(p + (size_t)r * W));
    }
    float hLv[10], hRv[10];
    if (HALO) {
#pragma unroll
        for (int k = 0; k < 10; ++k) {
            int r = i_begin - 1 + k; if (r > i_end + 1) r = i_end + 1;
            hLv[k] = hl ? __ldg(p + (size_t)r * W - 1) : 0.f;
            hRv[k] = hr ? __ldg(p + (size_t)r * W + 4) : 0.f;
        }
    }

    // ---- compute phase ----
    int sy = 0, sx = 0, sc = 0;
#pragma unroll
    for (int k = 1; k <= 8; ++k) {
        const int i = i_begin + k - 1;
        const float4 A = rv[k - 1], B = rv[k], C = rv[k + 1];

        const float vACx = fmaxf(A.x, C.x), vACy = fmaxf(A.y, C.y);
        const float vACz = fmaxf(A.z, C.z), vACw = fmaxf(A.w, C.w);
        const float m3x = fmaxf(vACx, B.x), m3y = fmaxf(vACy, B.y);
        const float m3z = fmaxf(vACz, B.z), m3w = fmaxf(vACw, B.w);

        float mL = __shfl_up_sync(shfl_mask, m3w, 1, LANE_W);
        float mR = __shfl_down_sync(shfl_mask, m3x, 1, LANE_W);
        if (HALO) {
            if (hl) mL = fmaxf(fmaxf(hLv[k - 1], hLv[k]), hLv[k + 1]);
            if (hr) mR = fmaxf(fmaxf(hRv[k - 1], hRv[k]), hRv[k + 1]);
        }

        const bool pk0 = !m0 && (B.x > vACx) && (B.x > mL)  && (B.x > m3y);
        const bool pk1 =        (B.y > vACy) && (B.y > m3x) && (B.y > m3z);
        const bool pk2 =        (B.z > vACz) && (B.z > m3y) && (B.z > m3w);
        const bool pk3 = !m3 && (B.w > vACw) && (B.w > m3z) && (B.w > mR);

        if (i <= i_end) {
            const int npk = (int)pk0 + (int)pk1 + (int)pk2 + (int)pk3;
            sc += npk;
            sy += i * npk;
            sx += col0 * npk + (int)pk1 + 2 * (int)pk2 + 3 * (int)pk3;
        }
    }

    // warp-wide reduction (both LANE_W=16 groups target the same batch n)
    sy = __reduce_add_sync(0xFFFFFFFFu, sy);
    sx = __reduce_add_sync(0xFFFFFFFFu, sx);
    sc = __reduce_add_sync(0xFFFFFFFFu, sc);
    if (lane == 0 && sc) {
        atomicAdd(&g_acc[n][0], R * sy);
        atomicAdd(&g_acc[n][1], R * sx);
        atomicAdd(&g_acc[n][2], sc);
    }
}

// ---------------------------------------------------------------------------
// Single fused kernel: peak detection (all 3 levels) + last-block finalize.
// 8-row strips. Global warp id w = blockIdx.x*4 + warpInBlock, 5376 total:
//   [0,4096):    p1 (256x256): n=w>>6; sub=w&63: cs=sub&1, rs=sub>>1 (0..31)
//   [4096,5120): p2 (128x128): t=w-4096: n=t>>4, rs=t&15
//   [5120,5376): p3 (64x64):   t=w-5120: n=t>>2, rs=t&3; two 16-lane groups,
//                              each an 8-row segment (seg = rs*2 + group)
// ---------------------------------------------------------------------------
__global__ void __launch_bounds__(128) offset_loss_kernel(
    const float* __restrict__ p1,
    const float* __restrict__ p2,
    const float* __restrict__ p3,
    const float* __restrict__ target,
    float* __restrict__ out)
{
    const int tid = threadIdx.x;

    // Block 0 computes target center sums first (hidden under other blocks' work).
    if (blockIdx.x == 0) {
        const int n = tid >> 1;        // 0..63
        const int q = tid & 1;         // 16 boxes each
        const float* tb = target + (size_t)n * 32 * 5 + q * 16 * 5;
        float t0 = 0.f, t1 = 0.f;
#pragma unroll
        for (int k = 0; k < 16; k++) {
            const float* b = tb + k * 5;
            t0 += (b[0] + b[2]) * 0.5f;
            t1 += (b[1] + b[3]) * 0.5f;
        }
        t0 += __shfl_xor_sync(0xFFFFFFFFu, t0, 1);
        t1 += __shfl_xor_sync(0xFFFFFFFFu, t1, 1);
        if (q == 0) {
            g_ts[n][0] = t0;
            g_ts[n][1] = t1;
            __threadfence();   // order before this block's g_done arrival
        }
    }

    // Strip work.
    const int w = blockIdx.x * 4 + (tid >> 5);
    if (w < 4096) {
        const int n = w >> 6;
        const int sub = w & 63;
        const int cs = sub & 1;
        const int rs = sub >> 1;
        const int i_begin = 1 + rs * 8;
        const int i_end = min(i_begin + 7, 254);
        const float* img = p1 + ((size_t)n * 3 + 2) * 65536;
        process_strip8<256, 4, 32>(img, n, i_begin, i_end, cs * 128);
    } else if (w < 5120) {
        const int t = w - 4096;
        const int n = t >> 4;
        const int rs = t & 15;
        const int i_begin = 1 + rs * 8;
        const int i_end = min(i_begin + 7, 126);
        const float* img = p2 + ((size_t)n * 3 + 2) * 16384;
        process_strip8<128, 8, 32>(img, n, i_begin, i_end, 0);
    } else {
        const int t = w - 5120;
        const int n = t >> 2;
        const int rs = t & 3;
        const int group = (tid & 31) >> 4;
        const int seg = rs * 2 + group;
        const int i_begin = 1 + seg * 8;
        const int i_end = min(i_begin + 7, 62);
        const float* img = p3 + ((size_t)n * 3 + 2) * 4096;
        process_strip8<64, 16, 16>(img, n, i_begin, i_end, 0);
    }

    // Arrival: last block finalizes.
    __shared__ int s_last;
    __syncthreads();
    if (tid == 0) {
        __threadfence();
        const int ticket = atomicAdd(&g_done, 1);
        s_last = (ticket == gridDim.x - 1) ? 1 : 0;
    }
    __syncthreads();
    if (!s_last) return;

    // ---- finalize (one block, 128 threads; threads 0..63 carry data) ----
    __threadfence();

    float off0 = 0.f, off1 = 0.f, cs0 = 0.f, cs1 = 0.f, ts0 = 0.f, ts1 = 0.f;
    int cnt = 0;
    if (tid < 64) {
        volatile int* acc = &g_acc[tid][0];
        const float c0 = (float)acc[0];   // center_sum[:,0]
        const float c1 = (float)acc[1];   // center_sum[:,1]
        cnt = acc[2];
        volatile float* ts = &g_ts[tid][0];
        ts0 = ts[0]; ts1 = ts[1];

        const float d0 = fabsf(c0 - ts0);
        const float d1 = fabsf(c1 - ts1);
        off0 = (d0 < 1.f) ? 0.5f * d0 * d0 : d0 - 0.5f;
        off1 = (d1 < 1.f) ? 0.5f * d1 * d1 : d1 - 0.5f;
        cs0 = c0; cs1 = c1;

        // reset accumulators for the next graph replay
        acc[0] = 0; acc[1] = 0; acc[2] = 0;
    }

    // reduce over 64 active threads (2 full warps; warps 2,3 contribute zeros)
#pragma unroll
    for (int d = 16; d > 0; d >>= 1) {
        off0 += __shfl_down_sync(0xFFFFFFFFu, off0, d);
        off1 += __shfl_down_sync(0xFFFFFFFFu, off1, d);
        cs0  += __shfl_down_sync(0xFFFFFFFFu, cs0, d);
        cs1  += __shfl_down_sync(0xFFFFFFFFu, cs1, d);
        ts0  += __shfl_down_sync(0xFFFFFFFFu, ts0, d);
        ts1  += __shfl_down_sync(0xFFFFFFFFu, ts1, d);
        cnt  += __shfl_down_sync(0xFFFFFFFFu, cnt, d);
    }
    __shared__ float sh[2][6];
    __shared__ int shc[2];
    if (tid < 64 && (tid & 31) == 0) {
        const int wg = tid >> 5;
        sh[wg][0] = off0; sh[wg][1] = off1; sh[wg][2] = cs0;
        sh[wg][3] = cs1;  sh[wg][4] = ts0;  sh[wg][5] = ts1;
        shc[wg] = cnt;
    }
    __syncthreads();
    if (tid == 0) {
        const float OFF0 = sh[0][0] + sh[1][0];
        const float OFF1 = sh[0][1] + sh[1][1];
        const float CS0  = sh[0][2] + sh[1][2];
        const float CS1  = sh[0][3] + sh[1][3];
        const float TS0  = sh[0][4] + sh[1][4];
        const float TS1  = sh[0][5] + sh[1][5];
        const float PSUM = (float)(shc[0] + shc[1]);
        out[0] = (OFF0 / fabsf(OFF0) * (CS0 - TS0) +
                  OFF1 / fabsf(OFF1) * (CS1 - TS1)) / PSUM;
        g_done = 0;   // reset arrival counter for next replay
    }
}

extern "C" void kernel_launch(void* const* d_in, const int* in_sizes, int n_in,
                              void* d_out, int out_size) {
    const float *p1 = nullptr, *p2 = nullptr, *p3 = nullptr, *tg = nullptr;
    for (int k = 0; k < n_in; k++) {
        switch (in_sizes[k]) {
            case 64 * 3 * 256 * 256: p1 = (const float*)d_in[k]; break;
            case 64 * 3 * 128 * 128: p2 = (const float*)d_in[k]; break;
            case 64 * 3 * 64 * 64:   p3 = (const float*)d_in[k]; break;
            case 64 * 32 * 5:        tg = (const float*)d_in[k]; break;
            default: break;
        }
    }

    // 5376 warps = 1344 blocks * 4 warps; single fused launch.
    offset_loss_kernel<<<1344, 128>>>(p1, p2, p3, tg, (float*)d_out);
}

// round 10
// speedup vs baseline: 1.1800x; 1.1800x over previous
#include <cuda_runtime.h>

// Per-batch exact integer accumulators: [n] = {sum_y(=Σ R*i), sum_x(=Σ R*j), count}
// Zero at module load; the final block re-zeroes after reading, so every graph
// replay starts clean (deterministic: integer adds are order-independent).
__device__ int g_acc[64][3];
__device__ float g_ts[64][2];   // target center sums, written by block 0 each run
__device__ int g_done;          // arrival counter, reset by the final block

// ---------------------------------------------------------------------------
// Software-pipelined 16-row strip: rows processed in 4-row chunks; the next
// chunk's 4 row-float4s are issued BEFORE computing the current chunk, keeping
// ~4 LDG.128 in flight per warp throughout.
// Peak(i,j) <=> B[j] > max(vAC[j], vm3[j-1], vm3[j+1]).
// ---------------------------------------------------------------------------
template<int W, int R, int LANE_W>
__device__ __forceinline__ void process_strip16(
    const float* __restrict__ img,   // channel-2 base for this batch
    int n, int i_begin, int i_end, int col_base)
{
    constexpr bool HALO = (4 * LANE_W < W);   // only p1 (two 128-col strips)
    const int lane = threadIdx.x & 31;
    const int li   = lane % LANE_W;
    const unsigned shfl_mask = (LANE_W == 32) ? 0xFFFFFFFFu
                                              : (0xFFFFu << (lane & 16));
    const int col0 = col_base + 4 * li;
    const bool hl = HALO && (col_base > 0) && (li == 0);
    const bool hr = HALO && (col_base + 4 * LANE_W < W) && (li == LANE_W - 1);
    const bool m0 = (col0 == 0);          // element 0 on image edge
    const bool m3 = (col0 + 3 == W - 1);  // element 3 on image edge
    const float* p  = img + col0;
    const bool  he  = hl || hr;           // edge lane needing a halo column
    const float* hp = hl ? (p - 1) : (p + 4);
    const int rmax = i_end + 1;           // clamp row index (dups hit L1)

    // cur[0..5] = rows (base-1 .. base+4) for the current 4-row chunk.
    float4 cur[6];
    float  hv[6];
#pragma unroll
    for (int k = 0; k < 6; ++k) {
        const int r = min(i_begin - 1 + k, rmax);
        cur[k] = __ldg((const float4*)(p + (size_t)r * W));
        if (HALO) hv[k] = he ? __ldg(hp + (size_t)r * W) : 0.f;
    }

    int sy = 0, sx = 0, sc = 0;

#pragma unroll
    for (int c = 0; c < 4; ++c) {
        // Prefetch next chunk's rows before computing this chunk.
        float4 nxt[4];
        float  nhv[4];
        if (c < 3) {
#pragma unroll
            for (int k = 0; k < 4; ++k) {
                const int r = min(i_begin + 5 + 4 * c + k, rmax);
                nxt[k] = __ldg((const float4*)(p + (size_t)r * W));
                if (HALO) nhv[k] = he ? __ldg(hp + (size_t)r * W) : 0.f;
            }
        }

        const int base = i_begin + 4 * c;
#pragma unroll
        for (int k = 0; k < 4; ++k) {
            const int i = base + k;
            const float4 A = cur[k], B = cur[k + 1], C = cur[k + 2];

            const float vACx = fmaxf(A.x, C.x), vACy = fmaxf(A.y, C.y);
            const float vACz = fmaxf(A.z, C.z), vACw = fmaxf(A.w, C.w);
            const float m3x = fmaxf(vACx, B.x), m3y = fmaxf(vACy, B.y);
            const float m3z = fmaxf(vACz, B.z), m3w = fmaxf(vACw, B.w);

            float mL = __shfl_up_sync(shfl_mask, m3w, 1, LANE_W);
            float mR = __shfl_down_sync(shfl_mask, m3x, 1, LANE_W);
            if (HALO) {
                const float hm = fmaxf(fmaxf(hv[k], hv[k + 1]), hv[k + 2]);
                if (hl) mL = hm;
                if (hr) mR = hm;
            }

            const bool pk0 = !m0 && (B.x > vACx) && (B.x > mL)  && (B.x > m3y);
            const bool pk1 =        (B.y > vACy) && (B.y > m3x) && (B.y > m3z);
            const bool pk2 =        (B.z > vACz) && (B.z > m3y) && (B.z > m3w);
            const bool pk3 = !m3 && (B.w > vACw) && (B.w > m3z) && (B.w > mR);

            if (i <= i_end) {
                const int npk = (int)pk0 + (int)pk1 + (int)pk2 + (int)pk3;
                sc += npk;
                sy += i * npk;
                sx += col0 * npk + (int)pk1 + 2 * (int)pk2 + 3 * (int)pk3;
            }
        }

        // Shift window: rows base+3, base+4 stay; append prefetched rows.
        if (c < 3) {
            cur[0] = cur[4]; cur[1] = cur[5];
#pragma unroll
            for (int k = 0; k < 4; ++k) cur[2 + k] = nxt[k];
            if (HALO) {
                hv[0] = hv[4]; hv[1] = hv[5];
#pragma unroll
                for (int k = 0; k < 4; ++k) hv[2 + k] = nhv[k];
            }
        }
    }

    // warp-wide reduction (both LANE_W=16 groups target the same batch n)
    sy = __reduce_add_sync(0xFFFFFFFFu, sy);
    sx = __reduce_add_sync(0xFFFFFFFFu, sx);
    sc = __reduce_add_sync(0xFFFFFFFFu, sc);
    if (lane == 0 && sc) {
        atomicAdd(&g_acc[n][0], R * sy);
        atomicAdd(&g_acc[n][1], R * sx);
        atomicAdd(&g_acc[n][2], sc);
    }
}

// ---------------------------------------------------------------------------
// Single fused kernel: peak detection (all 3 levels) + last-block finalize.
// 16-row strips. Global warp id w = blockIdx.x*8 + warpInBlock, 2688 total:
//   [0,2048):    p1 (256x256): n=w>>5; sub=w&31: cs=sub&1, rs=sub>>1
//   [2048,2560): p2 (128x128): t=w-2048: n=t>>3, rs=t&7
//   [2560,2688): p3 (64x64):   t=w-2560: n=t>>1, rs=t&1; two 16-lane groups,
//                              each a 16-row segment (seg = rs*2 + group)
// ---------------------------------------------------------------------------
__global__ void __launch_bounds__(256) offset_loss_kernel(
    const float* __restrict__ p1,
    const float* __restrict__ p2,
    const float* __restrict__ p3,
    const float* __restrict__ target,
    float* __restrict__ out)
{
    const int tid = threadIdx.x;

    // Block 0 computes target center sums first (hidden under other blocks' work).
    if (blockIdx.x == 0) {
        const int n = tid >> 2;
        const int q = tid & 3;
        const float* tb = target + (size_t)n * 32 * 5 + q * 8 * 5;
        float t0 = 0.f, t1 = 0.f;
#pragma unroll
        for (int k = 0; k < 8; k++) {
            const float* b = tb + k * 5;
            t0 += (b[0] + b[2]) * 0.5f;
            t1 += (b[1] + b[3]) * 0.5f;
        }
        t0 += __shfl_xor_sync(0xFFFFFFFFu, t0, 1);
        t1 += __shfl_xor_sync(0xFFFFFFFFu, t1, 1);
        t0 += __shfl_xor_sync(0xFFFFFFFFu, t0, 2);
        t1 += __shfl_xor_sync(0xFFFFFFFFu, t1, 2);
        if (q == 0) {
            g_ts[n][0] = t0;
            g_ts[n][1] = t1;
            __threadfence();   // order before this block's g_done arrival
        }
    }

    // Strip work.
    const int w = blockIdx.x * 8 + (tid >> 5);
    if (w < 2048) {
        const int n = w >> 5;
        const int sub = w & 31;
        const int cs = sub & 1;
        const int rs = sub >> 1;
        const int i_begin = 1 + rs * 16;
        const int i_end = min(i_begin + 15, 254);
        const float* img = p1 + ((size_t)n * 3 + 2) * 65536;
        process_strip16<256, 4, 32>(img, n, i_begin, i_end, cs * 128);
    } else if (w < 2560) {
        const int t = w - 2048;
        const int n = t >> 3;
        const int rs = t & 7;
        const int i_begin = 1 + rs * 16;
        const int i_end = min(i_begin + 15, 126);
        const float* img = p2 + ((size_t)n * 3 + 2) * 16384;
        process_strip16<128, 8, 32>(img, n, i_begin, i_end, 0);
    } else {
        const int t = w - 2560;
        const int n = t >> 1;
        const int rs = t & 1;
        const int group = (tid & 31) >> 4;
        const int seg = rs * 2 + group;
        const int i_begin = 1 + seg * 16;
        const int i_end = min(i_begin + 15, 62);
        const float* img = p3 + ((size_t)n * 3 + 2) * 4096;
        process_strip16<64, 16, 16>(img, n, i_begin, i_end, 0);
    }

    // Arrival: last block finalizes.
    __shared__ int s_last;
    __syncthreads();
    if (tid == 0) {
        __threadfence();
        const int ticket = atomicAdd(&g_done, 1);
        s_last = (ticket == gridDim.x - 1) ? 1 : 0;
    }
    __syncthreads();
    if (!s_last) return;

    // ---- finalize (one block; threads 0..63 carry data) ----
    __threadfence();

    float off0 = 0.f, off1 = 0.f, cs0 = 0.f, cs1 = 0.f, ts0 = 0.f, ts1 = 0.f;
    int cnt = 0;
    if (tid < 64) {
        volatile int* acc = &g_acc[tid][0];
        const float c0 = (float)acc[0];   // center_sum[:,0]
        const float c1 = (float)acc[1];   // center_sum[:,1]
        cnt = acc[2];
        volatile float* ts = &g_ts[tid][0];
        ts0 = ts[0]; ts1 = ts[1];

        const float d0 = fabsf(c0 - ts0);
        const float d1 = fabsf(c1 - ts1);
        off0 = (d0 < 1.f) ? 0.5f * d0 * d0 : d0 - 0.5f;
        off1 = (d1 < 1.f) ? 0.5f * d1 * d1 : d1 - 0.5f;
        cs0 = c0; cs1 = c1;

        // reset accumulators for the next graph replay
        acc[0] = 0; acc[1] = 0; acc[2] = 0;
    }

    // reduce over 64 active threads (2 full warps; higher warps contribute zeros)
#pragma unroll
    for (int d = 16; d > 0; d >>= 1) {
        off0 += __shfl_down_sync(0xFFFFFFFFu, off0, d);
        off1 += __shfl_down_sync(0xFFFFFFFFu, off1, d);
        cs0  += __shfl_down_sync(0xFFFFFFFFu, cs0, d);
        cs1  += __shfl_down_sync(0xFFFFFFFFu, cs1, d);
        ts0  += __shfl_down_sync(0xFFFFFFFFu, ts0, d);
        ts1  += __shfl_down_sync(0xFFFFFFFFu, ts1, d);
        cnt  += __shfl_down_sync(0xFFFFFFFFu, cnt, d);
    }
    __shared__ float sh[2][6];
    __shared__ int shc[2];
    if (tid < 64 && (tid & 31) == 0) {
        const int wg = tid >> 5;
        sh[wg][0] = off0; sh[wg][1] = off1; sh[wg][2] = cs0;
        sh[wg][3] = cs1;  sh[wg][4] = ts0;  sh[wg][5] = ts1;
        shc[wg] = cnt;
    }
    __syncthreads();
    if (tid == 0) {
        const float OFF0 = sh[0][0] + sh[1][0];
        const float OFF1 = sh[0][1] + sh[1][1];
        const float CS0  = sh[0][2] + sh[1][2];
        const float CS1  = sh[0][3] + sh[1][3];
        const float TS0  = sh[0][4] + sh[1][4];
        const float TS1  = sh[0][5] + sh[1][5];
        const float PSUM = (float)(shc[0] + shc[1]);
        out[0] = (OFF0 / fabsf(OFF0) * (CS0 - TS0) +
                  OFF1 / fabsf(OFF1) * (CS1 - TS1)) / PSUM;
        g_done = 0;   // reset arrival counter for next replay
    }
}

extern "C" void kernel_launch(void* const* d_in, const int* in_sizes, int n_in,
                              void* d_out, int out_size) {
    const float *p1 = nullptr, *p2 = nullptr, *p3 = nullptr, *tg = nullptr;
    for (int k = 0; k < n_in; k++) {
        switch (in_sizes[k]) {
            case 64 * 3 * 256 * 256: p1 = (const float*)d_in[k]; break;
            case 64 * 3 * 128 * 128: p2 = (const float*)d_in[k]; break;
            case 64 * 3 * 64 * 64:   p3 = (const float*)d_in[k]; break;
            case 64 * 32 * 5:        tg = (const float*)d_in[k]; break;
            default: break;
        }
    }

    // 2688 warps = 336 blocks * 8 warps; single wave; single fused launch.
    offset_loss_kernel<<<336, 256>>>(p1, p2, p3, tg, (float*)d_out);
}